// round 6
// baseline (speedup 1.0000x reference)
#include <cuda_runtime.h>
#include <cuda_bf16.h>
#include <cstdint>

// ============================================================================
// Problem constants
// ============================================================================
#define BB       512
#define TT       100          // K per batch
#define TPAD     112          // padded to 7 x k16
#define NPRE     256
#define NPOST    256
#define KTOT     (BB * TT)    // 51200
#define KSPLIT   74           // grid (74, 2, 2) = 296 CTAs = 2 per SM

// A tile (trace bf16, [p][t]): 128 rows, stride 240B (conflict-free: 240%128=112)
#define A_ROW_B   240
#define A_TILE_B  (128 * A_ROW_B)       // 30720
// B tile (post bf16, [t][q]): 112 rows x 128 bf16, stride 272B (272%128=16)
#define B_ROW_B   272
#define B_TILE_B  (TPAD * B_ROW_B)      // 30464

#define SM_A0     0
#define SM_A1     A_TILE_B                        // 30720
#define SM_B      (2 * A_TILE_B)                  // 61440
#define SM_SCAN   (2 * A_TILE_B + B_TILE_B)       // 91904
#define GEMM_SMEM (SM_SCAN + 128 * 4 + 128)       // 92544

// ============================================================================
// PTX helpers (baseline PTX only — tcgen05 unavailable on plain sm_103 target)
// ============================================================================
__device__ __forceinline__ void ldmatrix_x4(uint32_t* r, uint32_t addr) {
    asm volatile("ldmatrix.sync.aligned.m8n8.x4.shared.b16 {%0,%1,%2,%3}, [%4];"
                 : "=r"(r[0]), "=r"(r[1]), "=r"(r[2]), "=r"(r[3]) : "r"(addr));
}
__device__ __forceinline__ void ldmatrix_x4_trans(uint32_t* r, uint32_t addr) {
    asm volatile("ldmatrix.sync.aligned.m8n8.x4.trans.shared.b16 {%0,%1,%2,%3}, [%4];"
                 : "=r"(r[0]), "=r"(r[1]), "=r"(r[2]), "=r"(r[3]) : "r"(addr));
}
__device__ __forceinline__ void mma_16816(float* c, const uint32_t* a, const uint32_t* b) {
    asm volatile(
        "mma.sync.aligned.m16n8k16.row.col.f32.bf16.bf16.f32 "
        "{%0,%1,%2,%3}, {%4,%5,%6,%7}, {%8,%9}, {%0,%1,%2,%3};"
        : "+f"(c[0]), "+f"(c[1]), "+f"(c[2]), "+f"(c[3])
        : "r"(a[0]), "r"(a[1]), "r"(a[2]), "r"(a[3]), "r"(b[0]), "r"(b[1]));
}
__device__ __forceinline__ uint32_t smem_to_u32(const void* smem_ptr) {
    uint32_t addr;
    asm("{ .reg .u64 tmp; cvta.to.shared.u64 tmp, %1; cvt.u32.u64 %0, tmp; }"
        : "=r"(addr) : "l"(smem_ptr));
    return addr;
}
__device__ __forceinline__ uint32_t pack_bf16x2(float a, float b) {
    return ((uint32_t)__bfloat16_as_ushort(__float2bfloat16(b)) << 16)
         |  (uint32_t)__bfloat16_as_ushort(__float2bfloat16(a));
}

// ============================================================================
// Kernel 0: zero the output (d_out is poisoned; atomics need a clean base)
// ============================================================================
__global__ void stdp_zero_kernel(float4* __restrict__ out) {
    out[blockIdx.x * blockDim.x + threadIdx.x] = make_float4(0.f, 0.f, 0.f, 0.f);
}

// ============================================================================
// Fused kernel: trace scan + post convert + split-K bf16 HMMA GEMM
//   grid (74, mtile 2, ntile 2) = 296 CTAs (2/SM), 256 threads = 8 warps (2Mx4N)
//   CTA tile 128x128, warp tile 64x32. Epilogue: scaled RED atomics into d_out.
// ============================================================================
__global__ void __launch_bounds__(256, 2) stdp_fused_kernel(
    const float* __restrict__ pre, const float* __restrict__ post,
    float* __restrict__ out)
{
    extern __shared__ __align__(16) char smem[];
    const uint32_t su = smem_to_u32(smem);
    float* scanL = (float*)(smem + SM_SCAN);     // [128] carry hand-off

    const int tid    = threadIdx.x;
    const int wid    = tid >> 5;
    const int lane   = tid & 31;
    const int kid    = blockIdx.x;
    const int mtile  = blockIdx.y;
    const int ntile  = blockIdx.z;
    const int warp_m = wid >> 2;       // 0..1 (64 rows)
    const int warp_n = wid & 3;        // 0..3 (32 cols)

    // trace roles: p in [0,128), seg in {0,1} covering 50 t each
    const int tp   = tid & 127;
    const int tseg = tid >> 7;

    const float d = 0.95122942450071403f;   // exp(-1/20)

    // ---- zero pads once ----
    // A: both buffers contiguous (SM_A1 = SM_A0 + 128*240): rows 0..255, bytes [200,224)
    for (int i = tid; i < 256 * 6; i += 256) {
        int row = i / 6, off = (i % 6) * 4;
        *(uint32_t*)(smem + SM_A0 + row * A_ROW_B + 200 + off) = 0u;
    }
    // B: rows 100..111, bytes [0,256)
    for (int i = tid; i < 12 * 64; i += 256) {
        int row = 100 + i / 64, off = (i % 64) * 4;
        *(uint32_t*)(smem + SM_B + row * B_ROW_B + off) = 0u;
    }

    float acc[4][4][4];
    #pragma unroll
    for (int i = 0; i < 4; ++i)
        #pragma unroll
        for (int j = 0; j < 4; ++j)
            #pragma unroll
            for (int c = 0; c < 4; ++c) acc[i][j][c] = 0.0f;

    const int nb = (BB - kid + KSPLIT - 1) / KSPLIT;   // 6 or 7 batches

    // ---- prepare(batch, abuf): B fp32->bf16 convert + trace scan into A ----
    auto prepare = [&](int b, int abuf) {
        // B convert first: LDG.128 issue early, latency overlaps the scan chain
        {
            const float4* psrc = (const float4*)(post + (size_t)b * TT * NPOST + ntile * 128);
            #pragma unroll
            for (int it = 0; it < 13; ++it) {
                int f = tid + it * 256;
                if (f < 3200) {
                    int t = f >> 5, qg = f & 31;          // 32 float4 per row window
                    float4 v = psrc[t * 64 + qg];          // row stride 256 floats
                    uint2 pk = make_uint2(pack_bf16x2(v.x, v.y), pack_bf16x2(v.z, v.w));
                    *(uint2*)(smem + SM_B + t * B_ROW_B + qg * 8) = pk;
                }
            }
        }

        // trace: thread (tp, tseg) owns 50 consecutive t of its p
        const float* src = pre + ((size_t)b * TT + tseg * 50) * NPRE + mtile * 128 + tp;

        // phase 1: seg0 computes its decayed local sum (carry into seg1)
        if (tseg == 0) {
            float c = 0.0f;
            #pragma unroll
            for (int i = 0; i < 50; ++i)
                c = d * (c + src[(size_t)i * NPRE]);
            scanL[tp] = c;
        }
        __syncthreads();

        // phase 2: emit trace[t] = carry-before-t as bf16 into A [p][t]
        float C = tseg ? scanL[tp] : 0.0f;
        char* arow = smem + (abuf ? SM_A1 : SM_A0) + tp * A_ROW_B + tseg * 100;
        #pragma unroll
        for (int i = 0; i < 50; ++i) {
            *(__nv_bfloat16*)(arow + i * 2) = __float2bfloat16(C);
            C = d * (C + src[(size_t)i * NPRE]);
        }
    };

    __syncthreads();          // pads done
    prepare(kid, 0);          // batch 0
    __syncthreads();

    // ldmatrix lane addressing
    const int a_row  = (lane & 15);
    const int a_colh = (lane >> 4) * 8;
    const int bg  = lane >> 3;
    const int bl8 = lane & 7;
    const int b_krow = (bg & 1) * 8 + bl8;
    const int b_qoff = (bg >> 1) * 8;

    for (int j = 0; j < nb; ++j) {
        const int abuf = j & 1;
        const uint32_t A  = su + (abuf ? SM_A1 : SM_A0);
        const uint32_t Bb = su + SM_B;

        // ---- MMA over 7 k16 steps ----
        #pragma unroll
        for (int ks = 0; ks < 7; ++ks) {
            uint32_t afrag[4][4];
            uint32_t bfrag[4][2];
            #pragma unroll
            for (int mi = 0; mi < 4; ++mi) {
                uint32_t addr = A + (uint32_t)((warp_m * 64 + mi * 16 + a_row) * A_ROW_B
                                               + (a_colh + ks * 16) * 2);
                ldmatrix_x4(afrag[mi], addr);
            }
            #pragma unroll
            for (int nip = 0; nip < 2; ++nip) {
                uint32_t addr = Bb + (uint32_t)((ks * 16 + b_krow) * B_ROW_B
                                                + (warp_n * 32 + nip * 16 + b_qoff) * 2);
                uint32_t r[4];
                ldmatrix_x4_trans(r, addr);
                bfrag[nip * 2 + 0][0] = r[0]; bfrag[nip * 2 + 0][1] = r[1];
                bfrag[nip * 2 + 1][0] = r[2]; bfrag[nip * 2 + 1][1] = r[3];
            }
            #pragma unroll
            for (int mi = 0; mi < 4; ++mi)
                #pragma unroll
                for (int ni = 0; ni < 4; ++ni)
                    mma_16816(acc[mi][ni], afrag[mi], bfrag[ni]);
        }

        // ---- prepare next batch (B single-buffer: full sync fence) ----
        if (j + 1 < nb) {
            __syncthreads();                    // all warps done reading A/B of batch j
            prepare(kid + (j + 1) * KSPLIT, abuf ^ 1);
            __syncthreads();                    // tiles for j+1 visible
        }
    }

    // ---- epilogue: scale + RED atomics straight into d_out ----
    const float scale = (0.005f - 0.00525f) / (float)KTOT;
    const int p_base = mtile * 128 + warp_m * 64;
    const int q_base = ntile * 128 + warp_n * 32;
    #pragma unroll
    for (int mi = 0; mi < 4; ++mi) {
        #pragma unroll
        for (int ni = 0; ni < 4; ++ni) {
            int p0 = p_base + mi * 16 + (lane >> 2);
            int q  = q_base + ni * 8 + (lane & 3) * 2;
            float* o0 = out + (size_t)p0 * NPOST + q;
            float* o1 = out + (size_t)(p0 + 8) * NPOST + q;
            atomicAdd(o0,     acc[mi][ni][0] * scale);
            atomicAdd(o0 + 1, acc[mi][ni][1] * scale);
            atomicAdd(o1,     acc[mi][ni][2] * scale);
            atomicAdd(o1 + 1, acc[mi][ni][3] * scale);
        }
    }
}

// ============================================================================
// Launch
// ============================================================================
extern "C" void kernel_launch(void* const* d_in, const int* in_sizes, int n_in,
                              void* d_out, int out_size) {
    (void)in_sizes; (void)n_in; (void)out_size;
    const float* pre  = (const float*)d_in[0];
    const float* post = (const float*)d_in[1];
    float* out = (float*)d_out;

    cudaFuncSetAttribute(stdp_fused_kernel,
                         cudaFuncAttributeMaxDynamicSharedMemorySize, GEMM_SMEM);

    stdp_zero_kernel<<<64, 256>>>((float4*)out);   // 65536 floats
    stdp_fused_kernel<<<dim3(KSPLIT, 2, 2), 256, GEMM_SMEM>>>(pre, post, out);
}

// round 7
// speedup vs baseline: 1.2153x; 1.2153x over previous
#include <cuda_runtime.h>
#include <cuda_bf16.h>
#include <cstdint>

// ============================================================================
// Problem constants
// ============================================================================
#define BB       512
#define TT       100          // K per batch
#define TPAD     112          // padded to 7 x k16
#define NPRE     256
#define NPOST    256
#define KTOT     (BB * TT)    // 51200
#define KSPLIT   74           // grid (74, 2 mtiles) = 148 CTAs = one wave

// A tile (trace bf16, [p][t]): 128 rows, stride 240B
#define A_ROW_B   240
#define A_TILE_B  (128 * A_ROW_B)       // 30720
// B tile (post bf16, [t][q]): 112 rows x 256 bf16, stride 528B
#define B_ROW_B   528
#define B_TILE_B  (TPAD * B_ROW_B)      // 59136
// pre staging (fp32, [t][p]): 100 rows x 128 f32 (512B), stride 528B
#define STG_ROW_B 528
#define STG_B     (TT * STG_ROW_B)      // 52800

#define SM_A      0
#define SM_B      A_TILE_B                         // 30720
#define SM_STG    (A_TILE_B + B_TILE_B)            // 89856
#define SM_SCAN   (SM_STG + STG_B)                 // 142656
#define GEMM_SMEM (SM_SCAN + 3 * 128 * 4 + 128)    // 144320

// ============================================================================
// PTX helpers (baseline PTX only — tcgen05 unavailable on plain sm_103 target)
// ============================================================================
__device__ __forceinline__ void ldmatrix_x4(uint32_t* r, uint32_t addr) {
    asm volatile("ldmatrix.sync.aligned.m8n8.x4.shared.b16 {%0,%1,%2,%3}, [%4];"
                 : "=r"(r[0]), "=r"(r[1]), "=r"(r[2]), "=r"(r[3]) : "r"(addr));
}
__device__ __forceinline__ void ldmatrix_x4_trans(uint32_t* r, uint32_t addr) {
    asm volatile("ldmatrix.sync.aligned.m8n8.x4.trans.shared.b16 {%0,%1,%2,%3}, [%4];"
                 : "=r"(r[0]), "=r"(r[1]), "=r"(r[2]), "=r"(r[3]) : "r"(addr));
}
__device__ __forceinline__ void mma_16816(float* c, const uint32_t* a, const uint32_t* b) {
    asm volatile(
        "mma.sync.aligned.m16n8k16.row.col.f32.bf16.bf16.f32 "
        "{%0,%1,%2,%3}, {%4,%5,%6,%7}, {%8,%9}, {%0,%1,%2,%3};"
        : "+f"(c[0]), "+f"(c[1]), "+f"(c[2]), "+f"(c[3])
        : "r"(a[0]), "r"(a[1]), "r"(a[2]), "r"(a[3]), "r"(b[0]), "r"(b[1]));
}
__device__ __forceinline__ uint32_t smem_to_u32(const void* smem_ptr) {
    uint32_t addr;
    asm("{ .reg .u64 tmp; cvta.to.shared.u64 tmp, %1; cvt.u32.u64 %0, tmp; }"
        : "=r"(addr) : "l"(smem_ptr));
    return addr;
}
__device__ __forceinline__ void cp_async_16(uint32_t dst_smem, const void* src) {
    asm volatile("cp.async.cg.shared.global [%0], [%1], 16;"
                 :: "r"(dst_smem), "l"(src) : "memory");
}
#define CP_ASYNC_COMMIT() asm volatile("cp.async.commit_group;" ::: "memory")
#define CP_ASYNC_WAIT0()  asm volatile("cp.async.wait_group 0;" ::: "memory")

__device__ __forceinline__ uint32_t pack_bf16x2(float a, float b) {
    return ((uint32_t)__bfloat16_as_ushort(__float2bfloat16(b)) << 16)
         |  (uint32_t)__bfloat16_as_ushort(__float2bfloat16(a));
}

// ============================================================================
// Kernel 0: zero the output (d_out is poisoned; atomics need a clean base)
// ============================================================================
__global__ void stdp_zero_kernel(float4* __restrict__ out) {
    out[blockIdx.x * blockDim.x + threadIdx.x] = make_float4(0.f, 0.f, 0.f, 0.f);
}

// ============================================================================
// Fused kernel: cp.async pre staging + trace scan + post convert + HMMA GEMM
//   grid (74, mtile 2) = 148 CTAs, 512 threads = 16 warps (2 M x 8 N)
//   CTA tile 128x256 (M x N), K = one batch (100 -> pad 112) per iteration.
// ============================================================================
__global__ void __launch_bounds__(512, 1) stdp_fused_kernel(
    const float* __restrict__ pre, const float* __restrict__ post,
    float* __restrict__ out)
{
    extern __shared__ __align__(16) char smem[];
    const uint32_t su = smem_to_u32(smem);
    float* scanL = (float*)(smem + SM_SCAN);     // [3][128] segment sums
    float* stg   = (float*)(smem + SM_STG);      // [100][132] fp32 pre staging

    const int tid    = threadIdx.x;
    const int wid    = tid >> 5;
    const int lane   = tid & 31;
    const int kid    = blockIdx.x;
    const int mtile  = blockIdx.y;
    const int warp_m = wid >> 3;       // 0..1 (64 rows)
    const int warp_n = wid & 7;        // 0..7 (32 cols)

    // trace roles: p in [0,128), seg in [0,4) covering 25 t each
    const int tp   = tid & 127;
    const int tseg = tid >> 7;

    const float d   = 0.95122942450071403f;   // exp(-1/20)
    const float d25 = 0.28650479686019010f;   // exp(-25/20)

    // ---- zero pads once (prepare only writes t < 100) ----
    for (int i = tid; i < 128 * 6; i += 512) {            // A bytes [200,224) per p-row
        int row = i / 6, off = (i % 6) * 4;
        *(uint32_t*)(smem + SM_A + row * A_ROW_B + 200 + off) = 0u;
    }
    for (int i = tid; i < 12 * 128; i += 512) {           // B rows 100..111, 512B
        int row = 100 + i / 128, off = (i % 128) * 4;
        *(uint32_t*)(smem + SM_B + row * B_ROW_B + off) = 0u;
    }

    float acc[4][4][4];
    #pragma unroll
    for (int i = 0; i < 4; ++i)
        #pragma unroll
        for (int j = 0; j < 4; ++j)
            #pragma unroll
            for (int c = 0; c < 4; ++c) acc[i][j][c] = 0.0f;

    const int nb = (BB - kid + KSPLIT - 1) / KSPLIT;   // 6 or 7 batches

    // ---- issue cp.async: pre[b] tile [t][p] fp32 -> staging ----
    auto issue_pre = [&](int b) {
        const float* src = pre + (size_t)b * TT * NPRE + mtile * 128;
        #pragma unroll
        for (int it = 0; it < 7; ++it) {
            int f = tid + it * 512;
            if (f < 3200) {                     // 100 rows x 32 chunks of 16B
                int t = f >> 5, g = f & 31;
                cp_async_16(su + SM_STG + t * STG_ROW_B + g * 16,
                            src + (size_t)t * NPRE + g * 4);
            }
        }
        CP_ASYNC_COMMIT();
    };

    // ---- prepare(b): post LDG->bf16->B tile; trace scan staging->A tile ----
    auto prepare = [&](int b) {
        // post: 6400 float4 chunks, convert to bf16, STS into B [t][q]
        {
            const float4* psrc = (const float4*)(post + (size_t)b * TT * NPOST);
            #pragma unroll
            for (int it = 0; it < 13; ++it) {
                int f = tid + it * 512;
                if (f < 6400) {
                    int t = f >> 6, qg = f & 63;
                    float4 v = psrc[t * 64 + qg];
                    uint2 pk = make_uint2(pack_bf16x2(v.x, v.y), pack_bf16x2(v.z, v.w));
                    *(uint2*)(smem + SM_B + t * B_ROW_B + qg * 8) = pk;
                }
            }
        }

        // phase 1: segments 0..2 compute local decayed sums (25 steps, LDS)
        const int base = tseg * 25;
        if (tseg < 3) {
            float c = 0.0f;
            #pragma unroll
            for (int i = 0; i < 25; ++i)
                c = d * (c + stg[(base + i) * (STG_ROW_B / 4) + tp]);
            scanL[tseg * 128 + tp] = c;
        }
        __syncthreads();

        // carry into segment: C_s = sum_{u<s} d25^{s-1-u} * L_u
        float C = 0.0f;
        #pragma unroll
        for (int u = 0; u < 3; ++u)
            if (u < tseg) C = d25 * C + scanL[u * 128 + tp];

        // phase 2: emit trace[t] = carry-before-t as bf16 into A [p][t]
        char* arow = smem + SM_A + tp * A_ROW_B + tseg * 50;
        #pragma unroll
        for (int i = 0; i < 25; ++i) {
            *(__nv_bfloat16*)(arow + i * 2) = __float2bfloat16(C);
            C = d * (C + stg[(base + i) * (STG_ROW_B / 4) + tp]);
        }
    };

    // ---- prologue ----
    issue_pre(kid);
    CP_ASYNC_WAIT0();
    __syncthreads();          // pads + staging(0) ready
    prepare(kid);
    __syncthreads();

    // ldmatrix lane addressing
    const int a_row  = (lane & 15);
    const int a_colh = (lane >> 4) * 8;
    const int bg  = lane >> 3;
    const int bl8 = lane & 7;
    const int b_krow = (bg & 1) * 8 + bl8;
    const int b_qoff = (bg >> 1) * 8;

    const uint32_t A  = su + SM_A;
    const uint32_t Bb = su + SM_B;

    for (int j = 0; j < nb; ++j) {
        // prefetch next batch's pre (async, overlaps MMA below)
        if (j + 1 < nb)
            issue_pre(kid + (j + 1) * KSPLIT);

        // ---- MMA over 7 k16 steps ----
        #pragma unroll
        for (int ks = 0; ks < 7; ++ks) {
            uint32_t afrag[4][4];
            uint32_t bfrag[4][2];
            #pragma unroll
            for (int mi = 0; mi < 4; ++mi) {
                uint32_t addr = A + (uint32_t)((warp_m * 64 + mi * 16 + a_row) * A_ROW_B
                                               + (a_colh + ks * 16) * 2);
                ldmatrix_x4(afrag[mi], addr);
            }
            #pragma unroll
            for (int nip = 0; nip < 2; ++nip) {
                uint32_t addr = Bb + (uint32_t)((ks * 16 + b_krow) * B_ROW_B
                                                + (warp_n * 32 + nip * 16 + b_qoff) * 2);
                uint32_t r[4];
                ldmatrix_x4_trans(r, addr);
                bfrag[nip * 2 + 0][0] = r[0]; bfrag[nip * 2 + 0][1] = r[1];
                bfrag[nip * 2 + 1][0] = r[2]; bfrag[nip * 2 + 1][1] = r[3];
            }
            #pragma unroll
            for (int mi = 0; mi < 4; ++mi)
                #pragma unroll
                for (int ni = 0; ni < 4; ++ni)
                    mma_16816(acc[mi][ni], afrag[mi], bfrag[ni]);
        }

        // ---- build next batch's tiles ----
        if (j + 1 < nb) {
            CP_ASYNC_WAIT0();      // staging(j+1) landed
            __syncthreads();       // all warps done reading A/B of batch j
            prepare(kid + (j + 1) * KSPLIT);
            __syncthreads();       // tiles for j+1 visible
        }
    }

    // ---- epilogue: scale + RED atomics straight into d_out ----
    const float scale = (0.005f - 0.00525f) / (float)KTOT;
    const int p_base = mtile * 128 + warp_m * 64;
    const int q_base = warp_n * 32;
    #pragma unroll
    for (int mi = 0; mi < 4; ++mi) {
        #pragma unroll
        for (int ni = 0; ni < 4; ++ni) {
            int p0 = p_base + mi * 16 + (lane >> 2);
            int q  = q_base + ni * 8 + (lane & 3) * 2;
            float* o0 = out + (size_t)p0 * NPOST + q;
            float* o1 = out + (size_t)(p0 + 8) * NPOST + q;
            atomicAdd(o0,     acc[mi][ni][0] * scale);
            atomicAdd(o0 + 1, acc[mi][ni][1] * scale);
            atomicAdd(o1,     acc[mi][ni][2] * scale);
            atomicAdd(o1 + 1, acc[mi][ni][3] * scale);
        }
    }
}

// ============================================================================
// Launch
// ============================================================================
extern "C" void kernel_launch(void* const* d_in, const int* in_sizes, int n_in,
                              void* d_out, int out_size) {
    (void)in_sizes; (void)n_in; (void)out_size;
    const float* pre  = (const float*)d_in[0];
    const float* post = (const float*)d_in[1];
    float* out = (float*)d_out;

    cudaFuncSetAttribute(stdp_fused_kernel,
                         cudaFuncAttributeMaxDynamicSharedMemorySize, GEMM_SMEM);

    stdp_zero_kernel<<<64, 256>>>((float4*)out);   // 65536 floats
    stdp_fused_kernel<<<dim3(KSPLIT, 2), 512, GEMM_SMEM>>>(pre, post, out);
}

// round 8
// speedup vs baseline: 1.3711x; 1.1282x over previous
#include <cuda_runtime.h>
#include <cuda_bf16.h>
#include <cstdint>

// ============================================================================
// Problem constants
// ============================================================================
#define BB       512
#define TT       100          // K per batch
#define TPAD     112          // padded to 7 x k16
#define NPRE     256
#define NPOST    256
#define KTOT     (BB * TT)    // 51200
#define KSPLIT   74           // grid (74, 2 mtiles) = 148 CTAs = one wave

// A tile (trace bf16, [p][t]): 128 rows, stride 240B
#define A_ROW_B   240
#define A_TILE_B  (128 * A_ROW_B)       // 30720
// B tile (post bf16, [t][q]): 112 rows x 256 bf16, stride 528B
#define B_ROW_B   528
#define B_TILE_B  (TPAD * B_ROW_B)      // 59136
// pre staging (fp32, [t][p]): 104 rows (4 slack) x 128 f32, stride 528B
#define STG_ROW_B 528
#define STG_B     (104 * STG_ROW_B)     // 54912

#define SM_A      0
#define SM_B      A_TILE_B                         // 30720
#define SM_STG    (A_TILE_B + B_TILE_B)            // 89856
#define SM_SCAN   (SM_STG + STG_B)                 // 144768
#define GEMM_SMEM (SM_SCAN + 3 * 128 * 4 + 128)    // 146432

// ============================================================================
// PTX helpers (baseline PTX only — tcgen05 unavailable on plain sm_103 target)
// ============================================================================
__device__ __forceinline__ void ldmatrix_x4(uint32_t* r, uint32_t addr) {
    asm volatile("ldmatrix.sync.aligned.m8n8.x4.shared.b16 {%0,%1,%2,%3}, [%4];"
                 : "=r"(r[0]), "=r"(r[1]), "=r"(r[2]), "=r"(r[3]) : "r"(addr));
}
__device__ __forceinline__ void ldmatrix_x4_trans(uint32_t* r, uint32_t addr) {
    asm volatile("ldmatrix.sync.aligned.m8n8.x4.trans.shared.b16 {%0,%1,%2,%3}, [%4];"
                 : "=r"(r[0]), "=r"(r[1]), "=r"(r[2]), "=r"(r[3]) : "r"(addr));
}
__device__ __forceinline__ void mma_16816(float* c, const uint32_t* a, const uint32_t* b) {
    asm volatile(
        "mma.sync.aligned.m16n8k16.row.col.f32.bf16.bf16.f32 "
        "{%0,%1,%2,%3}, {%4,%5,%6,%7}, {%8,%9}, {%0,%1,%2,%3};"
        : "+f"(c[0]), "+f"(c[1]), "+f"(c[2]), "+f"(c[3])
        : "r"(a[0]), "r"(a[1]), "r"(a[2]), "r"(a[3]), "r"(b[0]), "r"(b[1]));
}
__device__ __forceinline__ uint32_t smem_to_u32(const void* smem_ptr) {
    uint32_t addr;
    asm("{ .reg .u64 tmp; cvta.to.shared.u64 tmp, %1; cvt.u32.u64 %0, tmp; }"
        : "=r"(addr) : "l"(smem_ptr));
    return addr;
}
__device__ __forceinline__ void cp_async_16(uint32_t dst_smem, const void* src) {
    asm volatile("cp.async.cg.shared.global [%0], [%1], 16;"
                 :: "r"(dst_smem), "l"(src) : "memory");
}
#define CP_ASYNC_COMMIT() asm volatile("cp.async.commit_group;" ::: "memory")
#define CP_ASYNC_WAIT0()  asm volatile("cp.async.wait_group 0;" ::: "memory")

__device__ __forceinline__ uint32_t pack_bf16x2(float a, float b) {
    return ((uint32_t)__bfloat16_as_ushort(__float2bfloat16(b)) << 16)
         |  (uint32_t)__bfloat16_as_ushort(__float2bfloat16(a));
}

// ============================================================================
// Kernel 0: zero the output (d_out is poisoned; atomics need a clean base)
// ============================================================================
__global__ void stdp_zero_kernel(float4* __restrict__ out) {
    out[blockIdx.x * blockDim.x + threadIdx.x] = make_float4(0.f, 0.f, 0.f, 0.f);
}

// ============================================================================
// Fused kernel: cp.async pre staging + reg-batched scan + latency-hidden post
//   convert + HMMA GEMM. grid (74, 2) = 148 CTAs, 512 threads (2M x 8N warps).
// ============================================================================
__global__ void __launch_bounds__(512, 1) stdp_fused_kernel(
    const float* __restrict__ pre, const float* __restrict__ post,
    float* __restrict__ out)
{
    extern __shared__ __align__(16) char smem[];
    const uint32_t su = smem_to_u32(smem);
    float* scanL = (float*)(smem + SM_SCAN);     // [3][128] segment sums
    float* stg   = (float*)(smem + SM_STG);      // [104][132] fp32 pre staging

    const int tid    = threadIdx.x;
    const int wid    = tid >> 5;
    const int lane   = tid & 31;
    const int kid    = blockIdx.x;
    const int mtile  = blockIdx.y;
    const int warp_m = wid >> 3;       // 0..1 (64 rows)
    const int warp_n = wid & 7;        // 0..7 (32 cols)

    // trace roles: p in [0,128), seg in [0,4): t-ranges 26/26/26/22
    const int tp   = tid & 127;
    const int tseg = tid >> 7;
    const int t0   = tseg * 26;
    const int seg_len = (tseg == 3) ? 22 : 26;

    const float d   = 0.95122942450071403f;   // exp(-1/20)
    const float d26 = 0.27253179303401259f;   // exp(-26/20)

    // ---- zero pads once (prepare only writes t < 100) ----
    for (int i = tid; i < 128 * 6; i += 512) {            // A bytes [200,224)
        int row = i / 6, off = (i % 6) * 4;
        *(uint32_t*)(smem + SM_A + row * A_ROW_B + 200 + off) = 0u;
    }
    for (int i = tid; i < 12 * 128; i += 512) {           // B rows 100..111
        int row = 100 + i / 128, off = (i % 128) * 4;
        *(uint32_t*)(smem + SM_B + row * B_ROW_B + off) = 0u;
    }

    float acc[4][4][4];
    #pragma unroll
    for (int i = 0; i < 4; ++i)
        #pragma unroll
        for (int j = 0; j < 4; ++j)
            #pragma unroll
            for (int c = 0; c < 4; ++c) acc[i][j][c] = 0.0f;

    const int nb = (BB - kid + KSPLIT - 1) / KSPLIT;   // 6 or 7 batches

    // ---- issue cp.async: pre[b] tile [t][p] fp32 -> staging ----
    auto issue_pre = [&](int b) {
        const float* src = pre + (size_t)b * TT * NPRE + mtile * 128;
        #pragma unroll
        for (int it = 0; it < 7; ++it) {
            int f = tid + it * 512;
            if (f < 3200) {                     // 100 rows x 32 chunks of 16B
                int t = f >> 5, g = f & 31;
                cp_async_16(su + SM_STG + t * STG_ROW_B + g * 16,
                            src + (size_t)t * NPRE + g * 4);
            }
        }
        CP_ASYNC_COMMIT();
    };

    // ---- prepare(b): latency-hidden post convert + reg-batched trace scan ----
    auto prepare = [&](int b) {
        const float4* psrc = (const float4*)(post + (size_t)b * TT * NPOST);

        // batched LDS of this thread's pre values into registers
        float xr[26];
        #pragma unroll
        for (int i = 0; i < 26; ++i)
            xr[i] = stg[(t0 + i) * (STG_ROW_B / 4) + tp];

        // issue post LDG half 1 (6 x float4); latency hides behind phase-1 chain
        float4 v0[6];
        #pragma unroll
        for (int it = 0; it < 6; ++it)
            v0[it] = psrc[tid + it * 512];       // f < 3072

        // phase 1: segments 0..2 local decayed sums (register chain)
        if (tseg < 3) {
            float c = 0.0f;
            #pragma unroll
            for (int i = 0; i < 26; ++i)
                c = d * (c + xr[i]);
            scanL[tseg * 128 + tp] = c;
        }

        // STS post half 1
        #pragma unroll
        for (int it = 0; it < 6; ++it) {
            int f = tid + it * 512;
            int t = f >> 6, qg = f & 63;
            *(uint2*)(smem + SM_B + t * B_ROW_B + qg * 8) =
                make_uint2(pack_bf16x2(v0[it].x, v0[it].y), pack_bf16x2(v0[it].z, v0[it].w));
        }

        // issue post LDG half 2 (7 x float4, last guarded); hides behind phase-2
        float4 v1[7];
        #pragma unroll
        for (int it = 0; it < 7; ++it) {
            int f = tid + (6 + it) * 512;        // 3072 .. 6655
            if (f < 6400) v1[it] = psrc[f];
        }

        __syncthreads();   // scanL visible

        // carry into segment: C_s = d26*( ... ) + L_{s-1}
        float C = 0.0f;
        #pragma unroll
        for (int u = 0; u < 3; ++u)
            if (u < tseg) C = d26 * C + scanL[u * 128 + tp];

        // phase 2: emit trace[t] = carry-before-t, packed STS.32 (seg_len even)
        char* arow = smem + SM_A + tp * A_ROW_B + t0 * 2;   // 4-aligned
        #pragma unroll
        for (int i = 0; i < 26; i += 2) {
            if (i < seg_len) {
                float c0 = C;
                C = d * (C + xr[i]);
                float c1 = C;
                C = d * (C + xr[i + 1]);
                *(uint32_t*)(arow + i * 2) = pack_bf16x2(c0, c1);
            }
        }

        // STS post half 2
        #pragma unroll
        for (int it = 0; it < 7; ++it) {
            int f = tid + (6 + it) * 512;
            if (f < 6400) {
                int t = f >> 6, qg = f & 63;
                *(uint2*)(smem + SM_B + t * B_ROW_B + qg * 8) =
                    make_uint2(pack_bf16x2(v1[it].x, v1[it].y), pack_bf16x2(v1[it].z, v1[it].w));
            }
        }
    };

    // ---- prologue ----
    issue_pre(kid);
    CP_ASYNC_WAIT0();
    __syncthreads();          // pads + staging(0) ready
    prepare(kid);
    __syncthreads();

    // ldmatrix lane addressing
    const int a_row  = (lane & 15);
    const int a_colh = (lane >> 4) * 8;
    const int bg  = lane >> 3;
    const int bl8 = lane & 7;
    const int b_krow = (bg & 1) * 8 + bl8;
    const int b_qoff = (bg >> 1) * 8;

    const uint32_t A  = su + SM_A;
    const uint32_t Bb = su + SM_B;

    for (int j = 0; j < nb; ++j) {
        // prefetch next batch's pre (async, overlaps MMA below)
        if (j + 1 < nb)
            issue_pre(kid + (j + 1) * KSPLIT);

        // ---- MMA over 7 k16 steps ----
        #pragma unroll
        for (int ks = 0; ks < 7; ++ks) {
            uint32_t afrag[4][4];
            uint32_t bfrag[4][2];
            #pragma unroll
            for (int mi = 0; mi < 4; ++mi) {
                uint32_t addr = A + (uint32_t)((warp_m * 64 + mi * 16 + a_row) * A_ROW_B
                                               + (a_colh + ks * 16) * 2);
                ldmatrix_x4(afrag[mi], addr);
            }
            #pragma unroll
            for (int nip = 0; nip < 2; ++nip) {
                uint32_t addr = Bb + (uint32_t)((ks * 16 + b_krow) * B_ROW_B
                                                + (warp_n * 32 + nip * 16 + b_qoff) * 2);
                uint32_t r[4];
                ldmatrix_x4_trans(r, addr);
                bfrag[nip * 2 + 0][0] = r[0]; bfrag[nip * 2 + 0][1] = r[1];
                bfrag[nip * 2 + 1][0] = r[2]; bfrag[nip * 2 + 1][1] = r[3];
            }
            #pragma unroll
            for (int mi = 0; mi < 4; ++mi)
                #pragma unroll
                for (int ni = 0; ni < 4; ++ni)
                    mma_16816(acc[mi][ni], afrag[mi], bfrag[ni]);
        }

        // ---- build next batch's tiles ----
        if (j + 1 < nb) {
            CP_ASYNC_WAIT0();      // staging(j+1) landed
            __syncthreads();       // all warps done reading A/B of batch j
            prepare(kid + (j + 1) * KSPLIT);
            __syncthreads();       // tiles for j+1 visible
        }
    }

    // ---- epilogue: scale + RED atomics straight into d_out ----
    const float scale = (0.005f - 0.00525f) / (float)KTOT;
    const int p_base = mtile * 128 + warp_m * 64;
    const int q_base = warp_n * 32;
    #pragma unroll
    for (int mi = 0; mi < 4; ++mi) {
        #pragma unroll
        for (int ni = 0; ni < 4; ++ni) {
            int p0 = p_base + mi * 16 + (lane >> 2);
            int q  = q_base + ni * 8 + (lane & 3) * 2;
            float* o0 = out + (size_t)p0 * NPOST + q;
            float* o1 = out + (size_t)(p0 + 8) * NPOST + q;
            atomicAdd(o0,     acc[mi][ni][0] * scale);
            atomicAdd(o0 + 1, acc[mi][ni][1] * scale);
            atomicAdd(o1,     acc[mi][ni][2] * scale);
            atomicAdd(o1 + 1, acc[mi][ni][3] * scale);
        }
    }
}

// ============================================================================
// Launch
// ============================================================================
extern "C" void kernel_launch(void* const* d_in, const int* in_sizes, int n_in,
                              void* d_out, int out_size) {
    (void)in_sizes; (void)n_in; (void)out_size;
    const float* pre  = (const float*)d_in[0];
    const float* post = (const float*)d_in[1];
    float* out = (float*)d_out;

    cudaFuncSetAttribute(stdp_fused_kernel,
                         cudaFuncAttributeMaxDynamicSharedMemorySize, GEMM_SMEM);

    stdp_zero_kernel<<<64, 256>>>((float4*)out);   // 65536 floats
    stdp_fused_kernel<<<dim3(KSPLIT, 2), 512, GEMM_SMEM>>>(pre, post, out);
}